// round 11
// baseline (speedup 1.0000x reference)
#include <cuda_runtime.h>
#include <cuda_bf16.h>
#include <cstdint>

typedef __nv_bfloat16 bf16;

// Problem-fixed sizes: N=50000, E=600000, EP=200000, D=128, L=3
constexpr int NMAX = 50000;
constexpr int EMAX = 600000;

// fp32 scratch (partials; U, V for predict)
__device__ __align__(16) float g_b0[NMAX * 128];
__device__ __align__(16) float g_b1[NMAX * 128];
// bf16 hi/lo node-feature pairs: 0=x, 1=p0, 2=p1, 3=ag
__device__ __align__(16) bf16 g_xh[NMAX * 128];
__device__ __align__(16) bf16 g_xl[NMAX * 128];
__device__ __align__(16) bf16 g_p0h[NMAX * 128];
__device__ __align__(16) bf16 g_p0l[NMAX * 128];
__device__ __align__(16) bf16 g_p1h[NMAX * 128];
__device__ __align__(16) bf16 g_p1l[NMAX * 128];
__device__ __align__(16) bf16 g_agh[NMAX * 128];
__device__ __align__(16) bf16 g_agl[NMAX * 128];
// Packed weights: 44 chunks x 4096 bf16 ([k=32][n=128] plain layout)
// 0-23: layers ([Wl(4) ; Wr(4)] per layer), 24-27: pW1, 28-31: qW1a,
// 32-35: qW1b, 36-39: W_U (composite), 40-43: W_V
__device__ __align__(16) bf16 g_wh[44 * 4096];
__device__ __align__(16) bf16 g_wl[44 * 4096];
__device__ float g_cvec[128];   // qb1 + pb2@qW1a + pb2@qW1b
// CSR
__device__ int   g_counts[NMAX];
__device__ int   g_offsets[NMAX];
__device__ int   g_cursor[NMAX];
__device__ float g_invdeg[NMAX];
__device__ int   g_csr[EMAX];
__device__ int   g_total;
__device__ int   g_ei64;
__device__ int   g_pi64;

__device__ __forceinline__ const bf16* pair_h(int s) {
    if (s == 0) return g_xh;
    if (s == 1) return g_p0h;
    if (s == 2) return g_p1h;
    return g_agh;
}
__device__ __forceinline__ const bf16* pair_l(int s) {
    if (s == 0) return g_xl;
    if (s == 1) return g_p0l;
    if (s == 2) return g_p1l;
    return g_agl;
}

__device__ __forceinline__ int getidx(const void* p, long long pos, int is64) {
    if (is64) return (int)((const long long*)p)[pos];
    return ((const int*)p)[pos];
}

__device__ __forceinline__ uint32_t smem_u32(const void* p) {
    uint32_t a;
    asm("{ .reg .u64 t; cvta.to.shared.u64 t, %1; cvt.u32.u64 %0, t; }" : "=r"(a) : "l"(p));
    return a;
}
__device__ __forceinline__ void ldmx4(uint32_t* r, uint32_t addr) {
    asm volatile("ldmatrix.sync.aligned.m8n8.x4.shared.b16 {%0,%1,%2,%3}, [%4];"
                 : "=r"(r[0]), "=r"(r[1]), "=r"(r[2]), "=r"(r[3]) : "r"(addr));
}
__device__ __forceinline__ void ldmx4t(uint32_t* r, uint32_t addr) {
    asm volatile("ldmatrix.sync.aligned.m8n8.x4.trans.shared.b16 {%0,%1,%2,%3}, [%4];"
                 : "=r"(r[0]), "=r"(r[1]), "=r"(r[2]), "=r"(r[3]) : "r"(addr));
}
__device__ __forceinline__ void mma16816(float* c, const uint32_t* a, const uint32_t* b) {
    asm volatile(
        "mma.sync.aligned.m16n8k16.row.col.f32.bf16.bf16.f32 "
        "{%0,%1,%2,%3}, {%4,%5,%6,%7}, {%8,%9}, {%0,%1,%2,%3};"
        : "+f"(c[0]), "+f"(c[1]), "+f"(c[2]), "+f"(c[3])
        : "r"(a[0]), "r"(a[1]), "r"(a[2]), "r"(a[3]), "r"(b[0]), "r"(b[1]));
}
__device__ __forceinline__ void cpasync16(uint32_t dst, const void* src, int srcsize) {
    asm volatile("cp.async.cg.shared.global [%0], [%1], 16, %2;"
                 :: "r"(dst), "l"(src), "r"(srcsize) : "memory");
}
#define CP_COMMIT() asm volatile("cp.async.commit_group;" ::: "memory")
#define CP_WAIT1()  asm volatile("cp.async.wait_group 1;" ::: "memory")
#define CP_WAIT0()  asm volatile("cp.async.wait_group 0;" ::: "memory")

// ---------------------------------------------------------------------------
// Weight prep: pack + transpose + bf16-split (36 input-derived chunks).
// ---------------------------------------------------------------------------
__global__ void prep_w_kernel(const float* __restrict__ Wl, const float* __restrict__ Wr,
                              const float* __restrict__ pW1, const float* __restrict__ qW1) {
    int t = blockIdx.x * blockDim.x + threadIdx.x;
    if (t >= 36 * 4096) return;
    int cg = t >> 12;
    int within = t & 4095;
    int kl = within >> 7;      // 0..31
    int n  = within & 127;
    float v;
    if (cg < 24) {
        int g = cg >> 3, c = cg & 7;
        int kk = c * 32 + kl;
        v = (kk < 128) ? Wl[g * 16384 + kk * 128 + n]
                       : Wr[g * 16384 + (kk - 128) * 128 + n];
    } else if (cg < 28) {
        int kk = (cg - 24) * 32 + kl;
        v = pW1[kk * 128 + n];
    } else if (cg < 32) {
        int kk = (cg - 28) * 32 + kl;
        v = qW1[kk * 128 + n];
    } else {
        int kk = (cg - 32) * 32 + kl;
        v = qW1[(128 + kk) * 128 + n];
    }
    bf16 hi = __float2bfloat16(v);
    bf16 lo = __float2bfloat16(v - __bfloat162float(hi));
    g_wh[cg * 4096 + kl * 128 + n] = hi;
    g_wl[cg * 4096 + kl * 128 + n] = lo;
}

// ---------------------------------------------------------------------------
// Composite weights fp32: W_U = pW2@qW1a (y=0), W_V = pW2@qW1b (y=1)
// ---------------------------------------------------------------------------
__global__ void composite_kernel(const float* __restrict__ pW2,
                                 const float* __restrict__ qW1) {
    __shared__ float row[128];
    int k = blockIdx.x, n = threadIdx.x;
    row[n] = pW2[k * 128 + n];
    __syncthreads();
    const float* Q = qW1 + (size_t)blockIdx.y * 128 * 128;
    float s = 0.f;
#pragma unroll 8
    for (int m = 0; m < 128; m++) s += row[m] * Q[m * 128 + n];
    bf16 hi = __float2bfloat16(s);
    bf16 lo = __float2bfloat16(s - __bfloat162float(hi));
    size_t off = (size_t)(36 + blockIdx.y * 4 + (k >> 5)) * 4096 +
                 (size_t)(k & 31) * 128 + n;
    g_wh[off] = hi;
    g_wl[off] = lo;
}

// ---------------------------------------------------------------------------
// Bias composition: cvec = qb1 + pb2@qW1a + pb2@qW1b
// ---------------------------------------------------------------------------
__global__ void cvec_kernel(const float* __restrict__ qW1,
                            const float* __restrict__ pb2,
                            const float* __restrict__ qb1) {
    int j = threadIdx.x;
    float c = qb1[j];
    for (int k = 0; k < 128; k++) {
        float p = pb2[k];
        c += p * (qW1[k * 128 + j] + qW1[(128 + k) * 128 + j]);
    }
    g_cvec[j] = c;
}

// ---------------------------------------------------------------------------
// Convert x (fp32) -> bf16 hi/lo pair (sel 0)
// ---------------------------------------------------------------------------
__global__ void convert_x_kernel(const float* __restrict__ x, int n32) {
    int i = blockIdx.x * blockDim.x + threadIdx.x;
    if (i >= n32) return;
    float4 v = ((const float4*)x)[i];
    bf16 h0 = __float2bfloat16(v.x), h1 = __float2bfloat16(v.y);
    bf16 h2 = __float2bfloat16(v.z), h3 = __float2bfloat16(v.w);
    bf16 l0 = __float2bfloat16(v.x - __bfloat162float(h0));
    bf16 l1 = __float2bfloat16(v.y - __bfloat162float(h1));
    bf16 l2 = __float2bfloat16(v.z - __bfloat162float(h2));
    bf16 l3 = __float2bfloat16(v.w - __bfloat162float(h3));
    __nv_bfloat162 hA = __halves2bfloat162(h0, h1), hB = __halves2bfloat162(h2, h3);
    __nv_bfloat162 lA = __halves2bfloat162(l0, l1), lB = __halves2bfloat162(l2, l3);
    ((uint2*)g_xh)[i] = make_uint2(*(uint32_t*)&hA, *(uint32_t*)&hB);
    ((uint2*)g_xl)[i] = make_uint2(*(uint32_t*)&lA, *(uint32_t*)&lB);
}

// ---------------------------------------------------------------------------
// Init / CSR build
// ---------------------------------------------------------------------------
__global__ void init_kernel(const unsigned int* __restrict__ eiw,
                            const unsigned int* __restrict__ piw, int n) {
    int i = blockIdx.x * blockDim.x + threadIdx.x;
    if (i < n) g_counts[i] = 0;
    if (blockIdx.x == 0) {
        unsigned ve = eiw[2 * threadIdx.x + 1];
        unsigned vp = piw[2 * threadIdx.x + 1];
        int e0 = __syncthreads_and(ve == 0u);
        int p0 = __syncthreads_and(vp == 0u);
        if (threadIdx.x == 0) { g_ei64 = e0; g_pi64 = p0; g_total = 0; }
    }
}

__global__ void count_kernel(const void* __restrict__ ei, int E) {
    int e = blockIdx.x * blockDim.x + threadIdx.x;
    if (e < E) atomicAdd(&g_counts[getidx(ei, (long long)E + e, g_ei64)], 1);
}

__global__ void segment_kernel(int n) {
    __shared__ int wsum[8];
    __shared__ int blockbase;
    int i = blockIdx.x * 256 + threadIdx.x;
    int lane = threadIdx.x & 31;
    int wid  = threadIdx.x >> 5;
    int c = (i < n) ? g_counts[i] : 0;
    int s = c;
#pragma unroll
    for (int off = 1; off < 32; off <<= 1) {
        int v = __shfl_up_sync(0xFFFFFFFFu, s, off);
        if (lane >= off) s += v;
    }
    if (lane == 31) wsum[wid] = s;
    __syncthreads();
    if (wid == 0) {
        int v = (lane < 8) ? wsum[lane] : 0;
#pragma unroll
        for (int off = 1; off < 8; off <<= 1) {
            int t2 = __shfl_up_sync(0xFFFFFFFFu, v, off);
            if (lane >= off) v += t2;
        }
        if (lane < 8) wsum[lane] = v;
        int total = __shfl_sync(0xFFFFFFFFu, v, 7);
        if (lane == 0) blockbase = atomicAdd(&g_total, total);
    }
    __syncthreads();
    if (i < n) {
        int excl = blockbase + (wid > 0 ? wsum[wid - 1] : 0) + s - c;
        g_offsets[i] = excl;
        g_cursor[i]  = excl;
        g_invdeg[i]  = 1.0f / (float)max(c, 1);
    }
}

__global__ void fill_kernel(const void* __restrict__ ei, int E) {
    int e = blockIdx.x * blockDim.x + threadIdx.x;
    if (e < E) {
        int s = getidx(ei, e, g_ei64);
        int d = getidx(ei, (long long)E + e, g_ei64);
        g_csr[atomicAdd(&g_cursor[d], 1)] = s;
    }
}

// ---------------------------------------------------------------------------
// Aggregation role (fused into GEMM kernel): warp-strided nodes, 2-edge unroll.
// ---------------------------------------------------------------------------
__device__ __noinline__ void do_aggr(int xsel, int n, int ab, int strideW) {
    int wid = threadIdx.x >> 5;
    int lane = threadIdx.x & 31;
    const bf16* xh = pair_h(xsel);
    const bf16* xl = pair_l(xsel);
    for (int w = ab * 8 + wid; w < n; w += strideW) {
        int beg = g_offsets[w];
        int end = beg + g_counts[w];
        float a0 = 0.f, a1 = 0.f, a2 = 0.f, a3 = 0.f;
        int j = beg;
        for (; j + 1 < end; j += 2) {
            int s0 = g_csr[j];
            int s1 = g_csr[j + 1];
            uint2 uh0 = *(const uint2*)(xh + (size_t)s0 * 128 + lane * 4);
            uint2 ul0 = *(const uint2*)(xl + (size_t)s0 * 128 + lane * 4);
            uint2 uh1 = *(const uint2*)(xh + (size_t)s1 * 128 + lane * 4);
            uint2 ul1 = *(const uint2*)(xl + (size_t)s1 * 128 + lane * 4);
            __nv_bfloat162 p;
            p = *(__nv_bfloat162*)&uh0.x; a0 += __low2float(p); a1 += __high2float(p);
            p = *(__nv_bfloat162*)&uh0.y; a2 += __low2float(p); a3 += __high2float(p);
            p = *(__nv_bfloat162*)&ul0.x; a0 += __low2float(p); a1 += __high2float(p);
            p = *(__nv_bfloat162*)&ul0.y; a2 += __low2float(p); a3 += __high2float(p);
            p = *(__nv_bfloat162*)&uh1.x; a0 += __low2float(p); a1 += __high2float(p);
            p = *(__nv_bfloat162*)&uh1.y; a2 += __low2float(p); a3 += __high2float(p);
            p = *(__nv_bfloat162*)&ul1.x; a0 += __low2float(p); a1 += __high2float(p);
            p = *(__nv_bfloat162*)&ul1.y; a2 += __low2float(p); a3 += __high2float(p);
        }
        if (j < end) {
            int s0 = g_csr[j];
            uint2 uh0 = *(const uint2*)(xh + (size_t)s0 * 128 + lane * 4);
            uint2 ul0 = *(const uint2*)(xl + (size_t)s0 * 128 + lane * 4);
            __nv_bfloat162 p;
            p = *(__nv_bfloat162*)&uh0.x; a0 += __low2float(p); a1 += __high2float(p);
            p = *(__nv_bfloat162*)&uh0.y; a2 += __low2float(p); a3 += __high2float(p);
            p = *(__nv_bfloat162*)&ul0.x; a0 += __low2float(p); a1 += __high2float(p);
            p = *(__nv_bfloat162*)&ul0.y; a2 += __low2float(p); a3 += __high2float(p);
        }
        float inv = g_invdeg[w];
        a0 *= inv; a1 *= inv; a2 *= inv; a3 *= inv;
        bf16 h0 = __float2bfloat16(a0), h1 = __float2bfloat16(a1);
        bf16 h2 = __float2bfloat16(a2), h3 = __float2bfloat16(a3);
        bf16 l0 = __float2bfloat16(a0 - __bfloat162float(h0));
        bf16 l1 = __float2bfloat16(a1 - __bfloat162float(h1));
        bf16 l2 = __float2bfloat16(a2 - __bfloat162float(h2));
        bf16 l3 = __float2bfloat16(a3 - __bfloat162float(h3));
        __nv_bfloat162 hA = __halves2bfloat162(h0, h1), hB = __halves2bfloat162(h2, h3);
        __nv_bfloat162 lA = __halves2bfloat162(l0, l1), lB = __halves2bfloat162(l2, l3);
        *(uint2*)(g_agh + (size_t)w * 128 + lane * 4) =
            make_uint2(*(uint32_t*)&hA, *(uint32_t*)&hB);
        *(uint2*)(g_agl + (size_t)w * 128 + lane * 4) =
            make_uint2(*(uint32_t*)&lA, *(uint32_t*)&lB);
    }
}

// ---------------------------------------------------------------------------
// Tensor-core GEMM (bf16 3-term split, fp32 accum), K=128, cp.async pipelined.
// Block 128x128, 8 warps, warp tile 32x64, 2 CTAs/SM.
// fuseaggr >= 0: odd blockIdx.x CTAs run the aggregation role instead.
// outmode 0: bf16 pair -> outsel; 1: fp32 -> g_b0/g_b1.
// addpartial: epilogue adds fp32 partial from g_b0.
// ---------------------------------------------------------------------------
constexpr int A_ST = 40;
constexpr int W_ST = 136;
constexpr int A_BUF = 128 * A_ST;
constexpr int W_BUF = 32 * W_ST;
constexpr int SBUF  = 2 * A_BUF + 2 * W_BUF;
constexpr int GEMM_SMEM_BYTES = 2 * SBUF * 2;     // 75776 bytes

__global__ void __launch_bounds__(256, 2)
gemm_mma(int a1sel, int wbase0, int wbase1,
         const float* __restrict__ bias, int relu, int outmode,
         int outsel0, int outsel1, int M,
         int fuseaggr, int gb, int addpartial) {
    extern __shared__ __align__(16) bf16 dyn[];

    int mb;
    if (fuseaggr >= 0) {
        if (blockIdx.x & 1) {
            do_aggr(fuseaggr, M, (int)(blockIdx.x >> 1), gb * 8);
            return;
        }
        mb = blockIdx.x >> 1;
    } else {
        mb = blockIdx.x;
    }

    const int wbase  = (blockIdx.y == 0) ? wbase0 : wbase1;
    const int outsel = (blockIdx.y == 0) ? outsel0 : outsel1;

    const int tid = threadIdx.x;
    const int wid = tid >> 5;
    const int lane = tid & 31;
    const int wr = wid >> 1;
    const int wc = wid & 1;
    const int m0 = mb * 128;
    const int lrow = lane & 15;
    const int lhalf = lane >> 4;

    const uint32_t dynb = smem_u32(dyn);
    const uint32_t bAh0 = dynb;
    const uint32_t bAl0 = dynb + A_BUF * 2;
    const uint32_t bWh0 = dynb + 2 * A_BUF * 2;
    const uint32_t bWl0 = dynb + (2 * A_BUF + W_BUF) * 2;
    const uint32_t bstep = SBUF * 2;

    const bf16* Ah = pair_h(a1sel);
    const bf16* Al = pair_l(a1sel);

    const int ar0 = tid >> 2, aq0 = (tid & 3) * 8;
    const int ar1 = (tid + 256) >> 2, aq1 = aq0;
    const int wr0 = tid >> 4, wq0 = (tid & 15) * 8;
    const int wr1 = (tid + 256) >> 4, wq1 = wq0;

    auto stage = [&](int cc, int b) {
        const int kbase = cc * 32;
        const bf16* wh = g_wh + (size_t)(wbase + cc) * 4096;
        const bf16* wl = g_wl + (size_t)(wbase + cc) * 4096;
        uint32_t base = (uint32_t)b * bstep;

        int gr0 = m0 + ar0, gr1 = m0 + ar1;
        int sz0 = (gr0 < M) ? 16 : 0;
        int sz1 = (gr1 < M) ? 16 : 0;
        int cg0 = min(gr0, M - 1), cg1 = min(gr1, M - 1);
        uint32_t d0 = (uint32_t)((ar0 * A_ST + aq0) * 2);
        uint32_t d1 = (uint32_t)((ar1 * A_ST + aq1) * 2);
        cpasync16(bAh0 + base + d0, Ah + (size_t)cg0 * 128 + kbase + aq0, sz0);
        cpasync16(bAh0 + base + d1, Ah + (size_t)cg1 * 128 + kbase + aq1, sz1);
        cpasync16(bAl0 + base + d0, Al + (size_t)cg0 * 128 + kbase + aq0, sz0);
        cpasync16(bAl0 + base + d1, Al + (size_t)cg1 * 128 + kbase + aq1, sz1);
        uint32_t e0 = (uint32_t)((wr0 * W_ST + wq0) * 2);
        uint32_t e1 = (uint32_t)((wr1 * W_ST + wq1) * 2);
        cpasync16(bWh0 + base + e0, wh + wr0 * 128 + wq0, 16);
        cpasync16(bWh0 + base + e1, wh + wr1 * 128 + wq1, 16);
        cpasync16(bWl0 + base + e0, wl + wr0 * 128 + wq0, 16);
        cpasync16(bWl0 + base + e1, wl + wr1 * 128 + wq1, 16);
    };

    float acc[2][8][4];
#pragma unroll
    for (int i = 0; i < 2; i++)
#pragma unroll
        for (int j = 0; j < 8; j++)
#pragma unroll
            for (int k = 0; k < 4; k++) acc[i][j][k] = 0.f;

    stage(0, 0);
    CP_COMMIT();

    for (int c = 0; c < 4; c++) {
        const int cb = c & 1;
        if (c + 1 < 4) {
            stage(c + 1, cb ^ 1);
            CP_COMMIT();
            CP_WAIT1();
        } else {
            CP_WAIT0();
        }
        __syncthreads();

        const uint32_t base = (uint32_t)cb * bstep;
        const uint32_t aH = bAh0 + base, aL = bAl0 + base;
        const uint32_t wH = bWh0 + base, wL = bWl0 + base;
#pragma unroll
        for (int ks = 0; ks < 2; ks++) {
            uint32_t fH[2][4], fL[2][4];
#pragma unroll
            for (int mt = 0; mt < 2; mt++) {
                uint32_t off = (uint32_t)(((32 * wr + 16 * mt + lrow) * A_ST +
                                           ks * 16 + 8 * lhalf) * 2);
                ldmx4(fH[mt], aH + off);
                ldmx4(fL[mt], aL + off);
            }
#pragma unroll
            for (int ng = 0; ng < 4; ng++) {
                uint32_t bH[4], bL[4];
                uint32_t off = (uint32_t)(((ks * 16 + lrow) * W_ST +
                                           64 * wc + 16 * ng + 8 * lhalf) * 2);
                ldmx4t(bH, wH + off);
                ldmx4t(bL, wL + off);
#pragma unroll
                for (int mt = 0; mt < 2; mt++) {
                    mma16816(acc[mt][2 * ng],     fH[mt], bH);
                    mma16816(acc[mt][2 * ng],     fH[mt], bL);
                    mma16816(acc[mt][2 * ng],     fL[mt], bH);
                    mma16816(acc[mt][2 * ng + 1], fH[mt], bH + 2);
                    mma16816(acc[mt][2 * ng + 1], fH[mt], bL + 2);
                    mma16816(acc[mt][2 * ng + 1], fL[mt], bH + 2);
                }
            }
        }
        __syncthreads();
    }

    // Epilogue
    float* Cf = (outmode == 1) ? ((outsel == 0) ? g_b0 : g_b1) : nullptr;
    bf16* oh = (outmode == 0) ? (bf16*)pair_h(outsel) : nullptr;
    bf16* ol = (outmode == 0) ? (bf16*)pair_l(outsel) : nullptr;

#pragma unroll
    for (int mt = 0; mt < 2; mt++) {
#pragma unroll
        for (int nt = 0; nt < 8; nt++) {
            int col = 64 * wc + 8 * nt + 2 * (lane & 3);
            float bb0 = bias ? bias[col] : 0.f;
            float bb1 = bias ? bias[col + 1] : 0.f;
#pragma unroll
            for (int h = 0; h < 2; h++) {
                int r = m0 + 32 * wr + 16 * mt + (lane >> 2) + 8 * h;
                if (r < M) {
                    float v0 = acc[mt][nt][2 * h]     + bb0;
                    float v1 = acc[mt][nt][2 * h + 1] + bb1;
                    if (addpartial) {
                        float2 p = *(const float2*)(g_b0 + (size_t)r * 128 + col);
                        v0 += p.x;
                        v1 += p.y;
                    }
                    if (relu) { v0 = fmaxf(v0, 0.f); v1 = fmaxf(v1, 0.f); }
                    if (outmode == 1) {
                        *(float2*)(Cf + (size_t)r * 128 + col) = make_float2(v0, v1);
                    } else {
                        bf16 h0 = __float2bfloat16(v0);
                        bf16 h1 = __float2bfloat16(v1);
                        bf16 l0 = __float2bfloat16(v0 - __bfloat162float(h0));
                        bf16 l1 = __float2bfloat16(v1 - __bfloat162float(h1));
                        __nv_bfloat162 hp = __halves2bfloat162(h0, h1);
                        __nv_bfloat162 lp = __halves2bfloat162(l0, l1);
                        *(uint32_t*)(oh + (size_t)r * 128 + col) = *(uint32_t*)&hp;
                        *(uint32_t*)(ol + (size_t)r * 128 + col) = *(uint32_t*)&lp;
                    }
                }
            }
        }
    }
}

// ---------------------------------------------------------------------------
// Edge predict: y[e] = relu(U[i] + V[j] + cvec) . qW2 + qb2  (one warp/edge)
// ---------------------------------------------------------------------------
__global__ void predict_kernel(const void* __restrict__ pidx,
                               const float* __restrict__ qW2,
                               const float* __restrict__ qb2,
                               float* __restrict__ y, int EP) {
    int w = (blockIdx.x * blockDim.x + threadIdx.x) >> 5;
    int lane = threadIdx.x & 31;
    if (w >= EP) return;
    int is64 = g_pi64;
    int i = getidx(pidx, w, is64);
    int j = getidx(pidx, (long long)EP + w, is64);
    float4 u = ((const float4*)g_b0)[i * 32 + lane];
    float4 v = ((const float4*)g_b1)[j * 32 + lane];
    float4 b = ((const float4*)g_cvec)[lane];
    float4 q = ((const float4*)qW2)[lane];
    float h0 = fmaxf(u.x + v.x + b.x, 0.f);
    float h1 = fmaxf(u.y + v.y + b.y, 0.f);
    float h2 = fmaxf(u.z + v.z + b.z, 0.f);
    float h3 = fmaxf(u.w + v.w + b.w, 0.f);
    float p = h0 * q.x + h1 * q.y + h2 * q.z + h3 * q.w;
#pragma unroll
    for (int o = 16; o > 0; o >>= 1) p += __shfl_xor_sync(0xFFFFFFFFu, p, o);
    if (lane == 0) y[w] = p + qb2[0];
}

// ---------------------------------------------------------------------------
// Launch
// ---------------------------------------------------------------------------
extern "C" void kernel_launch(void* const* d_in, const int* in_sizes, int n_in,
                              void* d_out, int out_size) {
    const float* x   = (const float*)d_in[0];
    const void*  ei  = d_in[2];
    const void*  pi  = d_in[3];
    const float* Wl  = (const float*)d_in[4];
    const float* bl  = (const float*)d_in[5];
    const float* Wr  = (const float*)d_in[6];
    // d_in[7..10]: edge-update MLP params — dead code w.r.t. the output
    const float* pW1 = (const float*)d_in[11];
    const float* pb1 = (const float*)d_in[12];
    const float* pW2 = (const float*)d_in[13];
    const float* pb2 = (const float*)d_in[14];
    const float* qW1 = (const float*)d_in[15];
    const float* qb1 = (const float*)d_in[16];
    const float* qW2 = (const float*)d_in[17];
    const float* qb2 = (const float*)d_in[18];

    const int N  = in_sizes[0] / 128;
    const int E  = in_sizes[2] / 2;
    const int EP = in_sizes[3] / 2;
    const int L  = in_sizes[4] / (128 * 128);

    cudaFuncSetAttribute(gemm_mma, cudaFuncAttributeMaxDynamicSharedMemorySize,
                         GEMM_SMEM_BYTES);

    // Weight pack + composites + x conversion (independent of CSR)
    prep_w_kernel<<<(36 * 4096 + 255) / 256, 256>>>(Wl, Wr, pW1, qW1);
    composite_kernel<<<dim3(128, 2), 128>>>(pW2, qW1);
    cvec_kernel<<<1, 128>>>(qW1, pb2, qb1);
    convert_x_kernel<<<(N * 32 + 255) / 256, 256>>>(x, N * 32);

    // CSR build
    init_kernel<<<(N + 255) / 256, 256>>>((const unsigned int*)ei,
                                          (const unsigned int*)pi, N);
    count_kernel<<<(E + 255) / 256, 256>>>(ei, E);
    segment_kernel<<<(N + 255) / 256, 256>>>(N);
    fill_kernel<<<(E + 255) / 256, 256>>>(ei, E);

    const int gb = (N + 127) / 128;   // 391

    // GNN layers: cur pair sel 0(x) -> 1 -> 2 -> 1
    int cur = 0;
    for (int l = 0; l < L; l++) {
        int nxt = (l == 0) ? 1 : (l == 1) ? 2 : 1;
        // A (fused): even CTAs cur@Wr + bl -> g_b0 (fp32); odd CTAs aggr(cur)->ag
        gemm_mma<<<dim3(2 * gb, 1), 256, GEMM_SMEM_BYTES>>>(
            cur, l * 8 + 4, 0, bl + l * 128, 0, 1, 0, 0, N, cur, gb, 0);
        // B: ag@Wl + partial -> relu -> nxt pair
        gemm_mma<<<dim3(gb, 1), 256, GEMM_SMEM_BYTES>>>(
            3, l * 8, 0, nullptr, 1, 0, nxt, 0, N, -1, gb, 1);
        cur = nxt;
    }
    // cur = 1. Post MLP first half: z = relu(p0@pW1 + pb1) -> sel 2
    gemm_mma<<<dim3(gb, 1), 256, GEMM_SMEM_BYTES>>>(
        1, 24, 0, pb1, 1, 0, 2, 0, N, -1, gb, 0);
    // U/V from z with composite weights: y=0 -> W_U -> g_b0 ; y=1 -> W_V -> g_b1
    gemm_mma<<<dim3(gb, 2), 256, GEMM_SMEM_BYTES>>>(
        2, 36, 40, nullptr, 0, 1, 0, 1, N, -1, gb, 0);

    predict_kernel<<<(EP * 32 + 255) / 256, 256>>>(pi, qW2, qb2, (float*)d_out, EP);
}

// round 12
// speedup vs baseline: 1.5659x; 1.5659x over previous
#include <cuda_runtime.h>
#include <cuda_bf16.h>
#include <cstdint>

typedef __nv_bfloat16 bf16;

// Problem-fixed sizes: N=50000, E=600000, EP=200000, D=128, L=3
constexpr int NMAX = 50000;
constexpr int EMAX = 600000;

// fp32 scratch (U, V for predict)
__device__ __align__(16) float g_b0[NMAX * 128];
__device__ __align__(16) float g_b1[NMAX * 128];
// bf16 hi/lo node-feature pairs: 0=x, 1=p0, 2=p1, 3=ag
__device__ __align__(16) bf16 g_xh[NMAX * 128];
__device__ __align__(16) bf16 g_xl[NMAX * 128];
__device__ __align__(16) bf16 g_p0h[NMAX * 128];
__device__ __align__(16) bf16 g_p0l[NMAX * 128];
__device__ __align__(16) bf16 g_p1h[NMAX * 128];
__device__ __align__(16) bf16 g_p1l[NMAX * 128];
__device__ __align__(16) bf16 g_agh[NMAX * 128];
__device__ __align__(16) bf16 g_agl[NMAX * 128];
// Packed weights: 44 chunks x 4096 bf16 ([k=32][n=128] plain layout)
// 0-23: layers ([Wl(4) ; Wr(4)] per layer), 24-27: pW1, 28-31: qW1a,
// 32-35: qW1b, 36-39: W_U (composite), 40-43: W_V
__device__ __align__(16) bf16 g_wh[44 * 4096];
__device__ __align__(16) bf16 g_wl[44 * 4096];
__device__ float g_cvec[128];   // qb1 + pb2@qW1a + pb2@qW1b
// CSR
__device__ int   g_counts[NMAX];
__device__ int   g_offsets[NMAX];
__device__ int   g_cursor[NMAX];
__device__ float g_invdeg[NMAX];
__device__ int   g_csr[EMAX];
__device__ int   g_total;
__device__ int   g_ei64;
__device__ int   g_pi64;

__device__ __forceinline__ const bf16* pair_h(int s) {
    if (s == 0) return g_xh;
    if (s == 1) return g_p0h;
    if (s == 2) return g_p1h;
    return g_agh;
}
__device__ __forceinline__ const bf16* pair_l(int s) {
    if (s == 0) return g_xl;
    if (s == 1) return g_p0l;
    if (s == 2) return g_p1l;
    return g_agl;
}

__device__ __forceinline__ int getidx(const void* p, long long pos, int is64) {
    if (is64) return (int)((const long long*)p)[pos];
    return ((const int*)p)[pos];
}

__device__ __forceinline__ uint32_t smem_u32(const void* p) {
    uint32_t a;
    asm("{ .reg .u64 t; cvta.to.shared.u64 t, %1; cvt.u32.u64 %0, t; }" : "=r"(a) : "l"(p));
    return a;
}
__device__ __forceinline__ void ldmx4(uint32_t* r, uint32_t addr) {
    asm volatile("ldmatrix.sync.aligned.m8n8.x4.shared.b16 {%0,%1,%2,%3}, [%4];"
                 : "=r"(r[0]), "=r"(r[1]), "=r"(r[2]), "=r"(r[3]) : "r"(addr));
}
__device__ __forceinline__ void ldmx4t(uint32_t* r, uint32_t addr) {
    asm volatile("ldmatrix.sync.aligned.m8n8.x4.trans.shared.b16 {%0,%1,%2,%3}, [%4];"
                 : "=r"(r[0]), "=r"(r[1]), "=r"(r[2]), "=r"(r[3]) : "r"(addr));
}
__device__ __forceinline__ void mma16816(float* c, const uint32_t* a, const uint32_t* b) {
    asm volatile(
        "mma.sync.aligned.m16n8k16.row.col.f32.bf16.bf16.f32 "
        "{%0,%1,%2,%3}, {%4,%5,%6,%7}, {%8,%9}, {%0,%1,%2,%3};"
        : "+f"(c[0]), "+f"(c[1]), "+f"(c[2]), "+f"(c[3])
        : "r"(a[0]), "r"(a[1]), "r"(a[2]), "r"(a[3]), "r"(b[0]), "r"(b[1]));
}
__device__ __forceinline__ void cpasync16(uint32_t dst, const void* src, int srcsize) {
    asm volatile("cp.async.cg.shared.global [%0], [%1], 16, %2;"
                 :: "r"(dst), "l"(src), "r"(srcsize) : "memory");
}
#define CP_COMMIT() asm volatile("cp.async.commit_group;" ::: "memory")
#define CP_WAIT1()  asm volatile("cp.async.wait_group 1;" ::: "memory")
#define CP_WAIT0()  asm volatile("cp.async.wait_group 0;" ::: "memory")

// ---------------------------------------------------------------------------
// Weight prep: pack + transpose + bf16-split (36 input-derived chunks).
// ---------------------------------------------------------------------------
__global__ void prep_w_kernel(const float* __restrict__ Wl, const float* __restrict__ Wr,
                              const float* __restrict__ pW1, const float* __restrict__ qW1) {
    int t = blockIdx.x * blockDim.x + threadIdx.x;
    if (t >= 36 * 4096) return;
    int cg = t >> 12;
    int within = t & 4095;
    int kl = within >> 7;      // 0..31
    int n  = within & 127;
    float v;
    if (cg < 24) {
        int g = cg >> 3, c = cg & 7;
        int kk = c * 32 + kl;
        v = (kk < 128) ? Wl[g * 16384 + kk * 128 + n]
                       : Wr[g * 16384 + (kk - 128) * 128 + n];
    } else if (cg < 28) {
        int kk = (cg - 24) * 32 + kl;
        v = pW1[kk * 128 + n];
    } else if (cg < 32) {
        int kk = (cg - 28) * 32 + kl;
        v = qW1[kk * 128 + n];
    } else {
        int kk = (cg - 32) * 32 + kl;
        v = qW1[(128 + kk) * 128 + n];
    }
    bf16 hi = __float2bfloat16(v);
    bf16 lo = __float2bfloat16(v - __bfloat162float(hi));
    g_wh[cg * 4096 + kl * 128 + n] = hi;
    g_wl[cg * 4096 + kl * 128 + n] = lo;
}

// ---------------------------------------------------------------------------
// Composite weights fp32: W_U = pW2@qW1a (y=0), W_V = pW2@qW1b (y=1)
// ---------------------------------------------------------------------------
__global__ void composite_kernel(const float* __restrict__ pW2,
                                 const float* __restrict__ qW1) {
    __shared__ float row[128];
    int k = blockIdx.x, n = threadIdx.x;
    row[n] = pW2[k * 128 + n];
    __syncthreads();
    const float* Q = qW1 + (size_t)blockIdx.y * 128 * 128;
    float s = 0.f;
#pragma unroll 8
    for (int m = 0; m < 128; m++) s += row[m] * Q[m * 128 + n];
    bf16 hi = __float2bfloat16(s);
    bf16 lo = __float2bfloat16(s - __bfloat162float(hi));
    size_t off = (size_t)(36 + blockIdx.y * 4 + (k >> 5)) * 4096 +
                 (size_t)(k & 31) * 128 + n;
    g_wh[off] = hi;
    g_wl[off] = lo;
}

// ---------------------------------------------------------------------------
// Bias composition: cvec = qb1 + pb2@qW1a + pb2@qW1b
// ---------------------------------------------------------------------------
__global__ void cvec_kernel(const float* __restrict__ qW1,
                            const float* __restrict__ pb2,
                            const float* __restrict__ qb1) {
    int j = threadIdx.x;
    float c = qb1[j];
    for (int k = 0; k < 128; k++) {
        float p = pb2[k];
        c += p * (qW1[k * 128 + j] + qW1[(128 + k) * 128 + j]);
    }
    g_cvec[j] = c;
}

// ---------------------------------------------------------------------------
// Convert x (fp32) -> bf16 hi/lo pair (sel 0)
// ---------------------------------------------------------------------------
__global__ void convert_x_kernel(const float* __restrict__ x, int n32) {
    int i = blockIdx.x * blockDim.x + threadIdx.x;
    if (i >= n32) return;
    float4 v = ((const float4*)x)[i];
    bf16 h0 = __float2bfloat16(v.x), h1 = __float2bfloat16(v.y);
    bf16 h2 = __float2bfloat16(v.z), h3 = __float2bfloat16(v.w);
    bf16 l0 = __float2bfloat16(v.x - __bfloat162float(h0));
    bf16 l1 = __float2bfloat16(v.y - __bfloat162float(h1));
    bf16 l2 = __float2bfloat16(v.z - __bfloat162float(h2));
    bf16 l3 = __float2bfloat16(v.w - __bfloat162float(h3));
    __nv_bfloat162 hA = __halves2bfloat162(h0, h1), hB = __halves2bfloat162(h2, h3);
    __nv_bfloat162 lA = __halves2bfloat162(l0, l1), lB = __halves2bfloat162(l2, l3);
    ((uint2*)g_xh)[i] = make_uint2(*(uint32_t*)&hA, *(uint32_t*)&hB);
    ((uint2*)g_xl)[i] = make_uint2(*(uint32_t*)&lA, *(uint32_t*)&lB);
}

// ---------------------------------------------------------------------------
// Init / CSR build
// ---------------------------------------------------------------------------
__global__ void init_kernel(const unsigned int* __restrict__ eiw,
                            const unsigned int* __restrict__ piw, int n) {
    int i = blockIdx.x * blockDim.x + threadIdx.x;
    if (i < n) g_counts[i] = 0;
    if (blockIdx.x == 0) {
        unsigned ve = eiw[2 * threadIdx.x + 1];
        unsigned vp = piw[2 * threadIdx.x + 1];
        int e0 = __syncthreads_and(ve == 0u);
        int p0 = __syncthreads_and(vp == 0u);
        if (threadIdx.x == 0) { g_ei64 = e0; g_pi64 = p0; g_total = 0; }
    }
}

__global__ void count_kernel(const void* __restrict__ ei, int E) {
    int e = blockIdx.x * blockDim.x + threadIdx.x;
    if (e < E) atomicAdd(&g_counts[getidx(ei, (long long)E + e, g_ei64)], 1);
}

__global__ void segment_kernel(int n) {
    __shared__ int wsum[8];
    __shared__ int blockbase;
    int i = blockIdx.x * 256 + threadIdx.x;
    int lane = threadIdx.x & 31;
    int wid  = threadIdx.x >> 5;
    int c = (i < n) ? g_counts[i] : 0;
    int s = c;
#pragma unroll
    for (int off = 1; off < 32; off <<= 1) {
        int v = __shfl_up_sync(0xFFFFFFFFu, s, off);
        if (lane >= off) s += v;
    }
    if (lane == 31) wsum[wid] = s;
    __syncthreads();
    if (wid == 0) {
        int v = (lane < 8) ? wsum[lane] : 0;
#pragma unroll
        for (int off = 1; off < 8; off <<= 1) {
            int t2 = __shfl_up_sync(0xFFFFFFFFu, v, off);
            if (lane >= off) v += t2;
        }
        if (lane < 8) wsum[lane] = v;
        int total = __shfl_sync(0xFFFFFFFFu, v, 7);
        if (lane == 0) blockbase = atomicAdd(&g_total, total);
    }
    __syncthreads();
    if (i < n) {
        int excl = blockbase + (wid > 0 ? wsum[wid - 1] : 0) + s - c;
        g_offsets[i] = excl;
        g_cursor[i]  = excl;
        g_invdeg[i]  = 1.0f / (float)max(c, 1);
    }
}

__global__ void fill_kernel(const void* __restrict__ ei, int E) {
    int e = blockIdx.x * blockDim.x + threadIdx.x;
    if (e < E) {
        int s = getidx(ei, e, g_ei64);
        int d = getidx(ei, (long long)E + e, g_ei64);
        g_csr[atomicAdd(&g_cursor[d], 1)] = s;
    }
}

// ---------------------------------------------------------------------------
// Mean aggregation over bf16 pairs -> ag bf16 pair. One warp/node.
// 4-edge unrolled CSR walk: 8 independent 8B loads in flight per lane.
// ---------------------------------------------------------------------------
__global__ void aggr_kernel(int xsel, int n) {
    int w = (blockIdx.x * blockDim.x + threadIdx.x) >> 5;
    int lane = threadIdx.x & 31;
    if (w >= n) return;
    const bf16* __restrict__ xh = pair_h(xsel);
    const bf16* __restrict__ xl = pair_l(xsel);
    int beg = g_offsets[w];
    int end = beg + g_counts[w];
    float a0 = 0.f, a1 = 0.f, a2 = 0.f, a3 = 0.f;
    int j = beg;
    for (; j + 3 < end; j += 4) {
        int s0 = g_csr[j], s1 = g_csr[j + 1], s2 = g_csr[j + 2], s3 = g_csr[j + 3];
        uint2 h0v = *(const uint2*)(xh + (size_t)s0 * 128 + lane * 4);
        uint2 l0v = *(const uint2*)(xl + (size_t)s0 * 128 + lane * 4);
        uint2 h1v = *(const uint2*)(xh + (size_t)s1 * 128 + lane * 4);
        uint2 l1v = *(const uint2*)(xl + (size_t)s1 * 128 + lane * 4);
        uint2 h2v = *(const uint2*)(xh + (size_t)s2 * 128 + lane * 4);
        uint2 l2v = *(const uint2*)(xl + (size_t)s2 * 128 + lane * 4);
        uint2 h3v = *(const uint2*)(xh + (size_t)s3 * 128 + lane * 4);
        uint2 l3v = *(const uint2*)(xl + (size_t)s3 * 128 + lane * 4);
        __nv_bfloat162 p;
        p = *(__nv_bfloat162*)&h0v.x; a0 += __low2float(p); a1 += __high2float(p);
        p = *(__nv_bfloat162*)&h0v.y; a2 += __low2float(p); a3 += __high2float(p);
        p = *(__nv_bfloat162*)&l0v.x; a0 += __low2float(p); a1 += __high2float(p);
        p = *(__nv_bfloat162*)&l0v.y; a2 += __low2float(p); a3 += __high2float(p);
        p = *(__nv_bfloat162*)&h1v.x; a0 += __low2float(p); a1 += __high2float(p);
        p = *(__nv_bfloat162*)&h1v.y; a2 += __low2float(p); a3 += __high2float(p);
        p = *(__nv_bfloat162*)&l1v.x; a0 += __low2float(p); a1 += __high2float(p);
        p = *(__nv_bfloat162*)&l1v.y; a2 += __low2float(p); a3 += __high2float(p);
        p = *(__nv_bfloat162*)&h2v.x; a0 += __low2float(p); a1 += __high2float(p);
        p = *(__nv_bfloat162*)&h2v.y; a2 += __low2float(p); a3 += __high2float(p);
        p = *(__nv_bfloat162*)&l2v.x; a0 += __low2float(p); a1 += __high2float(p);
        p = *(__nv_bfloat162*)&l2v.y; a2 += __low2float(p); a3 += __high2float(p);
        p = *(__nv_bfloat162*)&h3v.x; a0 += __low2float(p); a1 += __high2float(p);
        p = *(__nv_bfloat162*)&h3v.y; a2 += __low2float(p); a3 += __high2float(p);
        p = *(__nv_bfloat162*)&l3v.x; a0 += __low2float(p); a1 += __high2float(p);
        p = *(__nv_bfloat162*)&l3v.y; a2 += __low2float(p); a3 += __high2float(p);
    }
    for (; j < end; ++j) {
        int s0 = g_csr[j];
        uint2 h0v = *(const uint2*)(xh + (size_t)s0 * 128 + lane * 4);
        uint2 l0v = *(const uint2*)(xl + (size_t)s0 * 128 + lane * 4);
        __nv_bfloat162 p;
        p = *(__nv_bfloat162*)&h0v.x; a0 += __low2float(p); a1 += __high2float(p);
        p = *(__nv_bfloat162*)&h0v.y; a2 += __low2float(p); a3 += __high2float(p);
        p = *(__nv_bfloat162*)&l0v.x; a0 += __low2float(p); a1 += __high2float(p);
        p = *(__nv_bfloat162*)&l0v.y; a2 += __low2float(p); a3 += __high2float(p);
    }
    float inv = g_invdeg[w];
    a0 *= inv; a1 *= inv; a2 *= inv; a3 *= inv;
    bf16 h0 = __float2bfloat16(a0), h1 = __float2bfloat16(a1);
    bf16 h2 = __float2bfloat16(a2), h3 = __float2bfloat16(a3);
    bf16 l0 = __float2bfloat16(a0 - __bfloat162float(h0));
    bf16 l1 = __float2bfloat16(a1 - __bfloat162float(h1));
    bf16 l2 = __float2bfloat16(a2 - __bfloat162float(h2));
    bf16 l3 = __float2bfloat16(a3 - __bfloat162float(h3));
    __nv_bfloat162 hA = __halves2bfloat162(h0, h1), hB = __halves2bfloat162(h2, h3);
    __nv_bfloat162 lA = __halves2bfloat162(l0, l1), lB = __halves2bfloat162(l2, l3);
    *(uint2*)(g_agh + (size_t)w * 128 + lane * 4) =
        make_uint2(*(uint32_t*)&hA, *(uint32_t*)&hB);
    *(uint2*)(g_agl + (size_t)w * 128 + lane * 4) =
        make_uint2(*(uint32_t*)&lA, *(uint32_t*)&lB);
}

// ---------------------------------------------------------------------------
// Tensor-core GEMM via mma.sync (bf16 3-term split, fp32 accum).
// cp.async double-buffered. Block 128x128, 8 warps, warp tile 32x64.
// __launch_bounds__(256, 2): 2 CTAs/SM. Dual operand (a2sel>=0): K=256.
// ---------------------------------------------------------------------------
constexpr int A_ST = 40;
constexpr int W_ST = 136;
constexpr int A_BUF = 128 * A_ST;
constexpr int W_BUF = 32 * W_ST;
constexpr int SBUF  = 2 * A_BUF + 2 * W_BUF;
constexpr int GEMM_SMEM_BYTES = 2 * SBUF * 2;     // 75776 bytes

__global__ void __launch_bounds__(256, 2)
gemm_mma(int a1sel, int a2sel, int wbase0, int wbase1,
         const float* __restrict__ bias, int relu, int outmode,
         int outsel0, int outsel1, int M) {
    extern __shared__ __align__(16) bf16 dyn[];

    const int wbase  = (blockIdx.y == 0) ? wbase0 : wbase1;
    const int outsel = (blockIdx.y == 0) ? outsel0 : outsel1;

    const int tid = threadIdx.x;
    const int wid = tid >> 5;
    const int lane = tid & 31;
    const int wr = wid >> 1;
    const int wc = wid & 1;
    const int m0 = blockIdx.x * 128;
    const int lrow = lane & 15;
    const int lhalf = lane >> 4;

    const uint32_t dynb = smem_u32(dyn);
    const uint32_t bAh0 = dynb;
    const uint32_t bAl0 = dynb + A_BUF * 2;
    const uint32_t bWh0 = dynb + 2 * A_BUF * 2;
    const uint32_t bWl0 = dynb + (2 * A_BUF + W_BUF) * 2;
    const uint32_t bstep = SBUF * 2;

    const int nch = (a2sel < 0) ? 4 : 8;

    const int ar0 = tid >> 2, aq0 = (tid & 3) * 8;
    const int ar1 = (tid + 256) >> 2, aq1 = aq0;
    const int wr0 = tid >> 4, wq0 = (tid & 15) * 8;
    const int wr1 = (tid + 256) >> 4, wq1 = wq0;

    auto stage = [&](int cc, int b) {
        const int half = (nch == 8 && cc >= 4) ? 1 : 0;
        const int psel = half ? a2sel : a1sel;
        const bf16* Ah = pair_h(psel);
        const bf16* Al = pair_l(psel);
        const int kbase = (cc & 3) * 32;
        const bf16* wh = g_wh + (size_t)(wbase + cc) * 4096;
        const bf16* wl = g_wl + (size_t)(wbase + cc) * 4096;
        uint32_t base = (uint32_t)b * bstep;

        int gr0 = m0 + ar0, gr1 = m0 + ar1;
        int sz0 = (gr0 < M) ? 16 : 0;
        int sz1 = (gr1 < M) ? 16 : 0;
        int cg0 = min(gr0, M - 1), cg1 = min(gr1, M - 1);
        uint32_t d0 = (uint32_t)((ar0 * A_ST + aq0) * 2);
        uint32_t d1 = (uint32_t)((ar1 * A_ST + aq1) * 2);
        cpasync16(bAh0 + base + d0, Ah + (size_t)cg0 * 128 + kbase + aq0, sz0);
        cpasync16(bAh0 + base + d1, Ah + (size_t)cg1 * 128 + kbase + aq1, sz1);
        cpasync16(bAl0 + base + d0, Al + (size_t)cg0 * 128 + kbase + aq0, sz0);
        cpasync16(bAl0 + base + d1, Al + (size_t)cg1 * 128 + kbase + aq1, sz1);
        uint32_t e0 = (uint32_t)((wr0 * W_ST + wq0) * 2);
        uint32_t e1 = (uint32_t)((wr1 * W_ST + wq1) * 2);
        cpasync16(bWh0 + base + e0, wh + wr0 * 128 + wq0, 16);
        cpasync16(bWh0 + base + e1, wh + wr1 * 128 + wq1, 16);
        cpasync16(bWl0 + base + e0, wl + wr0 * 128 + wq0, 16);
        cpasync16(bWl0 + base + e1, wl + wr1 * 128 + wq1, 16);
    };

    float acc[2][8][4];
#pragma unroll
    for (int i = 0; i < 2; i++)
#pragma unroll
        for (int j = 0; j < 8; j++)
#pragma unroll
            for (int k = 0; k < 4; k++) acc[i][j][k] = 0.f;

    stage(0, 0);
    CP_COMMIT();

    for (int c = 0; c < nch; c++) {
        const int cb = c & 1;
        if (c + 1 < nch) {
            stage(c + 1, cb ^ 1);
            CP_COMMIT();
            CP_WAIT1();
        } else {
            CP_WAIT0();
        }
        __syncthreads();

        const uint32_t base = (uint32_t)cb * bstep;
        const uint32_t aH = bAh0 + base, aL = bAl0 + base;
        const uint32_t wH = bWh0 + base, wL = bWl0 + base;
#pragma unroll
        for (int ks = 0; ks < 2; ks++) {
            uint32_t fH[2][4], fL[2][4];
#pragma unroll
            for (int mt = 0; mt < 2; mt++) {
                uint32_t off = (uint32_t)(((32 * wr + 16 * mt + lrow) * A_ST +
                                           ks * 16 + 8 * lhalf) * 2);
                ldmx4(fH[mt], aH + off);
                ldmx4(fL[mt], aL + off);
            }
#pragma unroll
            for (int ng = 0; ng < 4; ng++) {
                uint32_t bH[4], bL[4];
                uint32_t off = (uint32_t)(((ks * 16 + lrow) * W_ST +
                                           64 * wc + 16 * ng + 8 * lhalf) * 2);
                ldmx4t(bH, wH + off);
                ldmx4t(bL, wL + off);
#pragma unroll
                for (int mt = 0; mt < 2; mt++) {
                    mma16816(acc[mt][2 * ng],     fH[mt], bH);
                    mma16816(acc[mt][2 * ng],     fH[mt], bL);
                    mma16816(acc[mt][2 * ng],     fL[mt], bH);
                    mma16816(acc[mt][2 * ng + 1], fH[mt], bH + 2);
                    mma16816(acc[mt][2 * ng + 1], fH[mt], bL + 2);
                    mma16816(acc[mt][2 * ng + 1], fL[mt], bH + 2);
                }
            }
        }
        __syncthreads();
    }

    // Epilogue
    float* Cf = (outmode == 1) ? ((outsel == 0) ? g_b0 : g_b1) : nullptr;
    bf16* oh = (outmode == 0) ? (bf16*)pair_h(outsel) : nullptr;
    bf16* ol = (outmode == 0) ? (bf16*)pair_l(outsel) : nullptr;

#pragma unroll
    for (int mt = 0; mt < 2; mt++) {
#pragma unroll
        for (int nt = 0; nt < 8; nt++) {
            int col = 64 * wc + 8 * nt + 2 * (lane & 3);
            float bb0 = bias ? bias[col] : 0.f;
            float bb1 = bias ? bias[col + 1] : 0.f;
#pragma unroll
            for (int h = 0; h < 2; h++) {
                int r = m0 + 32 * wr + 16 * mt + (lane >> 2) + 8 * h;
                if (r < M) {
                    float v0 = acc[mt][nt][2 * h]     + bb0;
                    float v1 = acc[mt][nt][2 * h + 1] + bb1;
                    if (relu) { v0 = fmaxf(v0, 0.f); v1 = fmaxf(v1, 0.f); }
                    if (outmode == 1) {
                        *(float2*)(Cf + (size_t)r * 128 + col) = make_float2(v0, v1);
                    } else {
                        bf16 h0 = __float2bfloat16(v0);
                        bf16 h1 = __float2bfloat16(v1);
                        bf16 l0 = __float2bfloat16(v0 - __bfloat162float(h0));
                        bf16 l1 = __float2bfloat16(v1 - __bfloat162float(h1));
                        __nv_bfloat162 hp = __halves2bfloat162(h0, h1);
                        __nv_bfloat162 lp = __halves2bfloat162(l0, l1);
                        *(uint32_t*)(oh + (size_t)r * 128 + col) = *(uint32_t*)&hp;
                        *(uint32_t*)(ol + (size_t)r * 128 + col) = *(uint32_t*)&lp;
                    }
                }
            }
        }
    }
}

// ---------------------------------------------------------------------------
// Edge predict: y[e] = relu(U[i] + V[j] + cvec) . qW2 + qb2  (one warp/edge)
// ---------------------------------------------------------------------------
__global__ void predict_kernel(const void* __restrict__ pidx,
                               const float* __restrict__ qW2,
                               const float* __restrict__ qb2,
                               float* __restrict__ y, int EP) {
    int w = (blockIdx.x * blockDim.x + threadIdx.x) >> 5;
    int lane = threadIdx.x & 31;
    if (w >= EP) return;
    int is64 = g_pi64;
    int i = getidx(pidx, w, is64);
    int j = getidx(pidx, (long long)EP + w, is64);
    float4 u = ((const float4*)g_b0)[i * 32 + lane];
    float4 v = ((const float4*)g_b1)[j * 32 + lane];
    float4 b = ((const float4*)g_cvec)[lane];
    float4 q = ((const float4*)qW2)[lane];
    float h0 = fmaxf(u.x + v.x + b.x, 0.f);
    float h1 = fmaxf(u.y + v.y + b.y, 0.f);
    float h2 = fmaxf(u.z + v.z + b.z, 0.f);
    float h3 = fmaxf(u.w + v.w + b.w, 0.f);
    float p = h0 * q.x + h1 * q.y + h2 * q.z + h3 * q.w;
#pragma unroll
    for (int o = 16; o > 0; o >>= 1) p += __shfl_xor_sync(0xFFFFFFFFu, p, o);
    if (lane == 0) y[w] = p + qb2[0];
}

// ---------------------------------------------------------------------------
// Launch
// ---------------------------------------------------------------------------
extern "C" void kernel_launch(void* const* d_in, const int* in_sizes, int n_in,
                              void* d_out, int out_size) {
    const float* x   = (const float*)d_in[0];
    const void*  ei  = d_in[2];
    const void*  pi  = d_in[3];
    const float* Wl  = (const float*)d_in[4];
    const float* bl  = (const float*)d_in[5];
    const float* Wr  = (const float*)d_in[6];
    // d_in[7..10]: edge-update MLP params — dead code w.r.t. the output
    const float* pW1 = (const float*)d_in[11];
    const float* pb1 = (const float*)d_in[12];
    const float* pW2 = (const float*)d_in[13];
    const float* pb2 = (const float*)d_in[14];
    const float* qW1 = (const float*)d_in[15];
    const float* qb1 = (const float*)d_in[16];
    const float* qW2 = (const float*)d_in[17];
    const float* qb2 = (const float*)d_in[18];

    const int N  = in_sizes[0] / 128;
    const int E  = in_sizes[2] / 2;
    const int EP = in_sizes[3] / 2;
    const int L  = in_sizes[4] / (128 * 128);

    cudaFuncSetAttribute(gemm_mma, cudaFuncAttributeMaxDynamicSharedMemorySize,
                         GEMM_SMEM_BYTES);

    // Weight pack + composites + x conversion (independent of CSR)
    prep_w_kernel<<<(36 * 4096 + 255) / 256, 256>>>(Wl, Wr, pW1, qW1);
    composite_kernel<<<dim3(128, 2), 128>>>(pW2, qW1);
    cvec_kernel<<<1, 128>>>(qW1, pb2, qb1);
    convert_x_kernel<<<(N * 32 + 255) / 256, 256>>>(x, N * 32);

    // CSR build
    init_kernel<<<(N + 255) / 256, 256>>>((const unsigned int*)ei,
                                          (const unsigned int*)pi, N);
    count_kernel<<<(E + 255) / 256, 256>>>(ei, E);
    segment_kernel<<<(N + 255) / 256, 256>>>(N);
    fill_kernel<<<(E + 255) / 256, 256>>>(ei, E);

    const int gb = (N + 127) / 128;   // 391
    const int aggr_blocks = (N * 32 + 255) / 256;

    // GNN layers: cur pair sel 0(x) -> 1 -> 2 -> 1
    int cur = 0;
    for (int l = 0; l < L; l++) {
        int nxt = (l == 0) ? 1 : (l == 1) ? 2 : 1;
        aggr_kernel<<<aggr_blocks, 256>>>(cur, N);
        gemm_mma<<<dim3(gb, 1), 256, GEMM_SMEM_BYTES>>>(
            3, cur, l * 8, 0, bl + l * 128, 1, 0, nxt, 0, N);
        cur = nxt;
    }
    // cur = 1. Post MLP first half: z = relu(p0@pW1 + pb1) -> sel 2
    gemm_mma<<<dim3(gb, 1), 256, GEMM_SMEM_BYTES>>>(
        1, -1, 24, 0, pb1, 1, 0, 2, 0, N);
    // U/V from z with composite weights: y=0 -> W_U -> g_b0 ; y=1 -> W_V -> g_b1
    gemm_mma<<<dim3(gb, 2), 256, GEMM_SMEM_BYTES>>>(
        2, -1, 36, 40, nullptr, 0, 1, 0, 1, N);

    predict_kernel<<<(EP * 32 + 255) / 256, 256>>>(pi, qW2, qb2, (float*)d_out, EP);
}

// round 13
// speedup vs baseline: 1.6307x; 1.0414x over previous
#include <cuda_runtime.h>
#include <cuda_bf16.h>
#include <cstdint>

typedef __nv_bfloat16 bf16;

// Problem-fixed sizes: N=50000, E=600000, EP=200000, D=128, L=3
constexpr int NMAX = 50000;
constexpr int EMAX = 600000;

// fp32 scratch (U, V for predict)
__device__ __align__(16) float g_b0[NMAX * 128];
__device__ __align__(16) float g_b1[NMAX * 128];
// bf16 hi/lo node-feature pairs: 0=x, 1=p0, 2=p1, 3=ag
__device__ __align__(16) bf16 g_xh[NMAX * 128];
__device__ __align__(16) bf16 g_xl[NMAX * 128];
__device__ __align__(16) bf16 g_p0h[NMAX * 128];
__device__ __align__(16) bf16 g_p0l[NMAX * 128];
__device__ __align__(16) bf16 g_p1h[NMAX * 128];
__device__ __align__(16) bf16 g_p1l[NMAX * 128];
__device__ __align__(16) bf16 g_agh[NMAX * 128];
__device__ __align__(16) bf16 g_agl[NMAX * 128];
// Packed weights: 44 chunks x 4096 bf16 ([k=32][n=128] plain layout)
// 0-23: layers ([Wl(4) ; Wr(4)] per layer), 24-27: pW1, 28-31: qW1a,
// 32-35: qW1b, 36-39: W_U (composite), 40-43: W_V
__device__ __align__(16) bf16 g_wh[44 * 4096];
__device__ __align__(16) bf16 g_wl[44 * 4096];
__device__ float g_cvec[128];   // qb1 + pb2@qW1a + pb2@qW1b
// CSR
__device__ int   g_counts[NMAX];
__device__ int   g_offsets[NMAX];
__device__ int   g_cursor[NMAX];
__device__ float g_invdeg[NMAX];
__device__ int   g_csr[EMAX];
__device__ int   g_total;
__device__ int   g_ei64;
__device__ int   g_pi64;

__device__ __forceinline__ const bf16* pair_h(int s) {
    if (s == 0) return g_xh;
    if (s == 1) return g_p0h;
    if (s == 2) return g_p1h;
    return g_agh;
}
__device__ __forceinline__ const bf16* pair_l(int s) {
    if (s == 0) return g_xl;
    if (s == 1) return g_p0l;
    if (s == 2) return g_p1l;
    return g_agl;
}

__device__ __forceinline__ int getidx(const void* p, long long pos, int is64) {
    if (is64) return (int)((const long long*)p)[pos];
    return ((const int*)p)[pos];
}

__device__ __forceinline__ uint32_t smem_u32(const void* p) {
    uint32_t a;
    asm("{ .reg .u64 t; cvta.to.shared.u64 t, %1; cvt.u32.u64 %0, t; }" : "=r"(a) : "l"(p));
    return a;
}
__device__ __forceinline__ void ldmx4(uint32_t* r, uint32_t addr) {
    asm volatile("ldmatrix.sync.aligned.m8n8.x4.shared.b16 {%0,%1,%2,%3}, [%4];"
                 : "=r"(r[0]), "=r"(r[1]), "=r"(r[2]), "=r"(r[3]) : "r"(addr));
}
__device__ __forceinline__ void ldmx4t(uint32_t* r, uint32_t addr) {
    asm volatile("ldmatrix.sync.aligned.m8n8.x4.trans.shared.b16 {%0,%1,%2,%3}, [%4];"
                 : "=r"(r[0]), "=r"(r[1]), "=r"(r[2]), "=r"(r[3]) : "r"(addr));
}
__device__ __forceinline__ void mma16816(float* c, const uint32_t* a, const uint32_t* b) {
    asm volatile(
        "mma.sync.aligned.m16n8k16.row.col.f32.bf16.bf16.f32 "
        "{%0,%1,%2,%3}, {%4,%5,%6,%7}, {%8,%9}, {%0,%1,%2,%3};"
        : "+f"(c[0]), "+f"(c[1]), "+f"(c[2]), "+f"(c[3])
        : "r"(a[0]), "r"(a[1]), "r"(a[2]), "r"(a[3]), "r"(b[0]), "r"(b[1]));
}
__device__ __forceinline__ void cpasync16(uint32_t dst, const void* src, int srcsize) {
    asm volatile("cp.async.cg.shared.global [%0], [%1], 16, %2;"
                 :: "r"(dst), "l"(src), "r"(srcsize) : "memory");
}
#define CP_COMMIT() asm volatile("cp.async.commit_group;" ::: "memory")
#define CP_WAIT1()  asm volatile("cp.async.wait_group 1;" ::: "memory")
#define CP_WAIT0()  asm volatile("cp.async.wait_group 0;" ::: "memory")

__device__ __forceinline__ void split_store(bf16* hp, bf16* lp, size_t idx,
                                            float v0, float v1) {
    bf16 h0 = __float2bfloat16(v0);
    bf16 h1 = __float2bfloat16(v1);
    bf16 l0 = __float2bfloat16(v0 - __bfloat162float(h0));
    bf16 l1 = __float2bfloat16(v1 - __bfloat162float(h1));
    __nv_bfloat162 hq = __halves2bfloat162(h0, h1);
    __nv_bfloat162 lq = __halves2bfloat162(l0, l1);
    *(uint32_t*)(hp + idx) = *(uint32_t*)&hq;
    *(uint32_t*)(lp + idx) = *(uint32_t*)&lq;
}

// ---------------------------------------------------------------------------
// Fused setup: one launch, blocks partitioned by role (all roles independent).
//  [0, B_CONV)                       convert_x
//  [B_CONV, +576)                    prep_w (36 chunks)
//  [.., +128)                        composite W_U / W_V (thread-split halves)
//  [.., +1)                          cvec
//  [.., +B_INIT)                     init counts (+ dtype detect in 1st block)
// ---------------------------------------------------------------------------
__global__ void setup_kernel(const float* __restrict__ x, int n32,
                             const float* __restrict__ Wl, const float* __restrict__ Wr,
                             const float* __restrict__ pW1, const float* __restrict__ pW2,
                             const float* __restrict__ qW1,
                             const float* __restrict__ pb2, const float* __restrict__ qb1,
                             const unsigned int* __restrict__ eiw,
                             const unsigned int* __restrict__ piw,
                             int n, int B_CONV, int B_INIT) {
    const int tid = threadIdx.x;
    int b = blockIdx.x;

    if (b < B_CONV) {
        // ---- convert_x ----
        int i = b * 256 + tid;
        if (i >= n32) return;
        float4 v = ((const float4*)x)[i];
        bf16 h0 = __float2bfloat16(v.x), h1 = __float2bfloat16(v.y);
        bf16 h2 = __float2bfloat16(v.z), h3 = __float2bfloat16(v.w);
        bf16 l0 = __float2bfloat16(v.x - __bfloat162float(h0));
        bf16 l1 = __float2bfloat16(v.y - __bfloat162float(h1));
        bf16 l2 = __float2bfloat16(v.z - __bfloat162float(h2));
        bf16 l3 = __float2bfloat16(v.w - __bfloat162float(h3));
        __nv_bfloat162 hA = __halves2bfloat162(h0, h1), hB = __halves2bfloat162(h2, h3);
        __nv_bfloat162 lA = __halves2bfloat162(l0, l1), lB = __halves2bfloat162(l2, l3);
        ((uint2*)g_xh)[i] = make_uint2(*(uint32_t*)&hA, *(uint32_t*)&hB);
        ((uint2*)g_xl)[i] = make_uint2(*(uint32_t*)&lA, *(uint32_t*)&lB);
        return;
    }
    b -= B_CONV;

    if (b < 576) {
        // ---- prep_w (36 chunks x 4096) ----
        int t = b * 256 + tid;
        int cg = t >> 12;
        int within = t & 4095;
        int kl = within >> 7;
        int nn = within & 127;
        float v;
        if (cg < 24) {
            int g = cg >> 3, c = cg & 7;
            int kk = c * 32 + kl;
            v = (kk < 128) ? Wl[g * 16384 + kk * 128 + nn]
                           : Wr[g * 16384 + (kk - 128) * 128 + nn];
        } else if (cg < 28) {
            int kk = (cg - 24) * 32 + kl;
            v = pW1[kk * 128 + nn];
        } else if (cg < 32) {
            int kk = (cg - 28) * 32 + kl;
            v = qW1[kk * 128 + nn];
        } else {
            int kk = (cg - 32) * 32 + kl;
            v = qW1[(128 + kk) * 128 + nn];
        }
        bf16 hi = __float2bfloat16(v);
        bf16 lo = __float2bfloat16(v - __bfloat162float(hi));
        g_wh[cg * 4096 + kl * 128 + nn] = hi;
        g_wl[cg * 4096 + kl * 128 + nn] = lo;
        return;
    }
    b -= 576;

    if (b < 128) {
        // ---- composite: k = b; threads 0-127 -> W_U, 128-255 -> W_V ----
        __shared__ float row[128];
        int k = b;
        if (tid < 128) row[tid] = pW2[k * 128 + tid];
        __syncthreads();
        int y = tid >> 7;              // 0 or 1
        int nn = tid & 127;
        const float* Q = qW1 + (size_t)y * 128 * 128;
        float s = 0.f;
#pragma unroll 8
        for (int m = 0; m < 128; m++) s += row[m] * Q[m * 128 + nn];
        bf16 hi = __float2bfloat16(s);
        bf16 lo = __float2bfloat16(s - __bfloat162float(hi));
        size_t off = (size_t)(36 + y * 4 + (k >> 5)) * 4096 +
                     (size_t)(k & 31) * 128 + nn;
        g_wh[off] = hi;
        g_wl[off] = lo;
        return;
    }
    b -= 128;

    if (b < 1) {
        // ---- cvec ----
        if (tid < 128) {
            float c = qb1[tid];
            for (int k = 0; k < 128; k++) {
                float p = pb2[k];
                c += p * (qW1[k * 128 + tid] + qW1[(128 + k) * 128 + tid]);
            }
            g_cvec[tid] = c;
        }
        return;
    }
    b -= 1;

    // ---- init counts (+ dtype detect in first block of this range) ----
    {
        int i = b * 256 + tid;
        if (i < n) g_counts[i] = 0;
        if (b == 0) {
            unsigned ve = eiw[2 * tid + 1];
            unsigned vp = piw[2 * tid + 1];
            int e0 = __syncthreads_and(ve == 0u);
            int p0 = __syncthreads_and(vp == 0u);
            if (tid == 0) { g_ei64 = e0; g_pi64 = p0; g_total = 0; }
        }
    }
}

// ---------------------------------------------------------------------------
// CSR build
// ---------------------------------------------------------------------------
__global__ void count_kernel(const void* __restrict__ ei, int E) {
    int e = blockIdx.x * blockDim.x + threadIdx.x;
    if (e < E) atomicAdd(&g_counts[getidx(ei, (long long)E + e, g_ei64)], 1);
}

__global__ void segment_kernel(int n) {
    __shared__ int wsum[8];
    __shared__ int blockbase;
    int i = blockIdx.x * 256 + threadIdx.x;
    int lane = threadIdx.x & 31;
    int wid  = threadIdx.x >> 5;
    int c = (i < n) ? g_counts[i] : 0;
    int s = c;
#pragma unroll
    for (int off = 1; off < 32; off <<= 1) {
        int v = __shfl_up_sync(0xFFFFFFFFu, s, off);
        if (lane >= off) s += v;
    }
    if (lane == 31) wsum[wid] = s;
    __syncthreads();
    if (wid == 0) {
        int v = (lane < 8) ? wsum[lane] : 0;
#pragma unroll
        for (int off = 1; off < 8; off <<= 1) {
            int t2 = __shfl_up_sync(0xFFFFFFFFu, v, off);
            if (lane >= off) v += t2;
        }
        if (lane < 8) wsum[lane] = v;
        int total = __shfl_sync(0xFFFFFFFFu, v, 7);
        if (lane == 0) blockbase = atomicAdd(&g_total, total);
    }
    __syncthreads();
    if (i < n) {
        int excl = blockbase + (wid > 0 ? wsum[wid - 1] : 0) + s - c;
        g_offsets[i] = excl;
        g_cursor[i]  = excl;
        g_invdeg[i]  = 1.0f / (float)max(c, 1);
    }
}

__global__ void fill_kernel(const void* __restrict__ ei, int E) {
    int e = blockIdx.x * blockDim.x + threadIdx.x;
    if (e < E) {
        int s = getidx(ei, e, g_ei64);
        int d = getidx(ei, (long long)E + e, g_ei64);
        g_csr[atomicAdd(&g_cursor[d], 1)] = s;
    }
}

// ---------------------------------------------------------------------------
// Mean aggregation over bf16 pairs -> ag bf16 pair. One warp/node,
// 4-edge unrolled.
// ---------------------------------------------------------------------------
__global__ void aggr_kernel(int xsel, int n) {
    int w = (blockIdx.x * blockDim.x + threadIdx.x) >> 5;
    int lane = threadIdx.x & 31;
    if (w >= n) return;
    const bf16* __restrict__ xh = pair_h(xsel);
    const bf16* __restrict__ xl = pair_l(xsel);
    int beg = g_offsets[w];
    int end = beg + g_counts[w];
    float a0 = 0.f, a1 = 0.f, a2 = 0.f, a3 = 0.f;
    int j = beg;
    for (; j + 3 < end; j += 4) {
        int s0 = g_csr[j], s1 = g_csr[j + 1], s2 = g_csr[j + 2], s3 = g_csr[j + 3];
        uint2 h0v = *(const uint2*)(xh + (size_t)s0 * 128 + lane * 4);
        uint2 l0v = *(const uint2*)(xl + (size_t)s0 * 128 + lane * 4);
        uint2 h1v = *(const uint2*)(xh + (size_t)s1 * 128 + lane * 4);
        uint2 l1v = *(const uint2*)(xl + (size_t)s1 * 128 + lane * 4);
        uint2 h2v = *(const uint2*)(xh + (size_t)s2 * 128 + lane * 4);
        uint2 l2v = *(const uint2*)(xl + (size_t)s2 * 128 + lane * 4);
        uint2 h3v = *(const uint2*)(xh + (size_t)s3 * 128 + lane * 4);
        uint2 l3v = *(const uint2*)(xl + (size_t)s3 * 128 + lane * 4);
        __nv_bfloat162 p;
        p = *(__nv_bfloat162*)&h0v.x; a0 += __low2float(p); a1 += __high2float(p);
        p = *(__nv_bfloat162*)&h0v.y; a2 += __low2float(p); a3 += __high2float(p);
        p = *(__nv_bfloat162*)&l0v.x; a0 += __low2float(p); a1 += __high2float(p);
        p = *(__nv_bfloat162*)&l0v.y; a2 += __low2float(p); a3 += __high2float(p);
        p = *(__nv_bfloat162*)&h1v.x; a0 += __low2float(p); a1 += __high2float(p);
        p = *(__nv_bfloat162*)&h1v.y; a2 += __low2float(p); a3 += __high2float(p);
        p = *(__nv_bfloat162*)&l1v.x; a0 += __low2float(p); a1 += __high2float(p);
        p = *(__nv_bfloat162*)&l1v.y; a2 += __low2float(p); a3 += __high2float(p);
        p = *(__nv_bfloat162*)&h2v.x; a0 += __low2float(p); a1 += __high2float(p);
        p = *(__nv_bfloat162*)&h2v.y; a2 += __low2float(p); a3 += __high2float(p);
        p = *(__nv_bfloat162*)&l2v.x; a0 += __low2float(p); a1 += __high2float(p);
        p = *(__nv_bfloat162*)&l2v.y; a2 += __low2float(p); a3 += __high2float(p);
        p = *(__nv_bfloat162*)&h3v.x; a0 += __low2float(p); a1 += __high2float(p);
        p = *(__nv_bfloat162*)&h3v.y; a2 += __low2float(p); a3 += __high2float(p);
        p = *(__nv_bfloat162*)&l3v.x; a0 += __low2float(p); a1 += __high2float(p);
        p = *(__nv_bfloat162*)&l3v.y; a2 += __low2float(p); a3 += __high2float(p);
    }
    for (; j < end; ++j) {
        int s0 = g_csr[j];
        uint2 h0v = *(const uint2*)(xh + (size_t)s0 * 128 + lane * 4);
        uint2 l0v = *(const uint2*)(xl + (size_t)s0 * 128 + lane * 4);
        __nv_bfloat162 p;
        p = *(__nv_bfloat162*)&h0v.x; a0 += __low2float(p); a1 += __high2float(p);
        p = *(__nv_bfloat162*)&h0v.y; a2 += __low2float(p); a3 += __high2float(p);
        p = *(__nv_bfloat162*)&l0v.x; a0 += __low2float(p); a1 += __high2float(p);
        p = *(__nv_bfloat162*)&l0v.y; a2 += __low2float(p); a3 += __high2float(p);
    }
    float inv = g_invdeg[w];
    a0 *= inv; a1 *= inv; a2 *= inv; a3 *= inv;
    split_store(g_agh, g_agl, (size_t)w * 128 + lane * 4, a0, a1);
    split_store(g_agh, g_agl, (size_t)w * 128 + lane * 4 + 2, a2, a3);
}

// ---------------------------------------------------------------------------
// Tensor-core GEMM via mma.sync (bf16 3-term split, fp32 accum).
// cp.async double-buffered. Block 128x128, 8 warps, warp tile 32x64.
// __launch_bounds__(256, 2): 2 CTAs/SM. Dual operand (a2sel>=0): K=256.
// ---------------------------------------------------------------------------
constexpr int A_ST = 40;
constexpr int W_ST = 136;
constexpr int A_BUF = 128 * A_ST;
constexpr int W_BUF = 32 * W_ST;
constexpr int SBUF  = 2 * A_BUF + 2 * W_BUF;
constexpr int GEMM_SMEM_BYTES = 2 * SBUF * 2;     // 75776 bytes

__global__ void __launch_bounds__(256, 2)
gemm_mma(int a1sel, int a2sel, int wbase0, int wbase1,
         const float* __restrict__ bias, int relu, int outmode,
         int outsel0, int outsel1, int M) {
    extern __shared__ __align__(16) bf16 dyn[];

    const int wbase  = (blockIdx.y == 0) ? wbase0 : wbase1;
    const int outsel = (blockIdx.y == 0) ? outsel0 : outsel1;

    const int tid = threadIdx.x;
    const int wid = tid >> 5;
    const int lane = tid & 31;
    const int wr = wid >> 1;
    const int wc = wid & 1;
    const int m0 = blockIdx.x * 128;
    const int lrow = lane & 15;
    const int lhalf = lane >> 4;

    const uint32_t dynb = smem_u32(dyn);
    const uint32_t bAh0 = dynb;
    const uint32_t bAl0 = dynb + A_BUF * 2;
    const uint32_t bWh0 = dynb + 2 * A_BUF * 2;
    const uint32_t bWl0 = dynb + (2 * A_BUF + W_BUF) * 2;
    const uint32_t bstep = SBUF * 2;

    const int nch = (a2sel < 0) ? 4 : 8;

    const int ar0 = tid >> 2, aq0 = (tid & 3) * 8;
    const int ar1 = (tid + 256) >> 2, aq1 = aq0;
    const int wr0 = tid >> 4, wq0 = (tid & 15) * 8;
    const int wr1 = (tid + 256) >> 4, wq1 = wq0;

    auto stage = [&](int cc, int b) {
        const int half = (nch == 8 && cc >= 4) ? 1 : 0;
        const int psel = half ? a2sel : a1sel;
        const bf16* Ah = pair_h(psel);
        const bf16* Al = pair_l(psel);
        const int kbase = (cc & 3) * 32;
        const bf16* wh = g_wh + (size_t)(wbase + cc) * 4096;
        const bf16* wl = g_wl + (size_t)(wbase + cc) * 4096;
        uint32_t base = (uint32_t)b * bstep;

        int gr0 = m0 + ar0, gr1 = m0 + ar1;
        int sz0 = (gr0 < M) ? 16 : 0;
        int sz1 = (gr1 < M) ? 16 : 0;
        int cg0 = min(gr0, M - 1), cg1 = min(gr1, M - 1);
        uint32_t d0 = (uint32_t)((ar0 * A_ST + aq0) * 2);
        uint32_t d1 = (uint32_t)((ar1 * A_ST + aq1) * 2);
        cpasync16(bAh0 + base + d0, Ah + (size_t)cg0 * 128 + kbase + aq0, sz0);
        cpasync16(bAh0 + base + d1, Ah + (size_t)cg1 * 128 + kbase + aq1, sz1);
        cpasync16(bAl0 + base + d0, Al + (size_t)cg0 * 128 + kbase + aq0, sz0);
        cpasync16(bAl0 + base + d1, Al + (size_t)cg1 * 128 + kbase + aq1, sz1);
        uint32_t e0 = (uint32_t)((wr0 * W_ST + wq0) * 2);
        uint32_t e1 = (uint32_t)((wr1 * W_ST + wq1) * 2);
        cpasync16(bWh0 + base + e0, wh + wr0 * 128 + wq0, 16);
        cpasync16(bWh0 + base + e1, wh + wr1 * 128 + wq1, 16);
        cpasync16(bWl0 + base + e0, wl + wr0 * 128 + wq0, 16);
        cpasync16(bWl0 + base + e1, wl + wr1 * 128 + wq1, 16);
    };

    float acc[2][8][4];
#pragma unroll
    for (int i = 0; i < 2; i++)
#pragma unroll
        for (int j = 0; j < 8; j++)
#pragma unroll
            for (int k = 0; k < 4; k++) acc[i][j][k] = 0.f;

    stage(0, 0);
    CP_COMMIT();

    for (int c = 0; c < nch; c++) {
        const int cb = c & 1;
        if (c + 1 < nch) {
            stage(c + 1, cb ^ 1);
            CP_COMMIT();
            CP_WAIT1();
        } else {
            CP_WAIT0();
        }
        __syncthreads();

        const uint32_t base = (uint32_t)cb * bstep;
        const uint32_t aH = bAh0 + base, aL = bAl0 + base;
        const uint32_t wH = bWh0 + base, wL = bWl0 + base;
#pragma unroll
        for (int ks = 0; ks < 2; ks++) {
            uint32_t fH[2][4], fL[2][4];
#pragma unroll
            for (int mt = 0; mt < 2; mt++) {
                uint32_t off = (uint32_t)(((32 * wr + 16 * mt + lrow) * A_ST +
                                           ks * 16 + 8 * lhalf) * 2);
                ldmx4(fH[mt], aH + off);
                ldmx4(fL[mt], aL + off);
            }
#pragma unroll
            for (int ng = 0; ng < 4; ng++) {
                uint32_t bH[4], bL[4];
                uint32_t off = (uint32_t)(((ks * 16 + lrow) * W_ST +
                                           64 * wc + 16 * ng + 8 * lhalf) * 2);
                ldmx4t(bH, wH + off);
                ldmx4t(bL, wL + off);
#pragma unroll
                for (int mt = 0; mt < 2; mt++) {
                    mma16816(acc[mt][2 * ng],     fH[mt], bH);
                    mma16816(acc[mt][2 * ng],     fH[mt], bL);
                    mma16816(acc[mt][2 * ng],     fL[mt], bH);
                    mma16816(acc[mt][2 * ng + 1], fH[mt], bH + 2);
                    mma16816(acc[mt][2 * ng + 1], fH[mt], bL + 2);
                    mma16816(acc[mt][2 * ng + 1], fL[mt], bH + 2);
                }
            }
        }
        __syncthreads();
    }

    // Epilogue
    float* Cf = (outmode == 1) ? ((outsel == 0) ? g_b0 : g_b1) : nullptr;
    bf16* oh = (outmode == 0) ? (bf16*)pair_h(outsel) : nullptr;
    bf16* ol = (outmode == 0) ? (bf16*)pair_l(outsel) : nullptr;

#pragma unroll
    for (int mt = 0; mt < 2; mt++) {
#pragma unroll
        for (int nt = 0; nt < 8; nt++) {
            int col = 64 * wc + 8 * nt + 2 * (lane & 3);
            float bb0 = bias ? bias[col] : 0.f;
            float bb1 = bias ? bias[col + 1] : 0.f;
#pragma unroll
            for (int h = 0; h < 2; h++) {
                int r = m0 + 32 * wr + 16 * mt + (lane >> 2) + 8 * h;
                if (r < M) {
                    float v0 = acc[mt][nt][2 * h]     + bb0;
                    float v1 = acc[mt][nt][2 * h + 1] + bb1;
                    if (relu) { v0 = fmaxf(v0, 0.f); v1 = fmaxf(v1, 0.f); }
                    if (outmode == 1) {
                        *(float2*)(Cf + (size_t)r * 128 + col) = make_float2(v0, v1);
                    } else {
                        split_store(oh, ol, (size_t)r * 128 + col, v0, v1);
                    }
                }
            }
        }
    }
}

// ---------------------------------------------------------------------------
// Edge predict: y[e] = relu(U[i] + V[j] + cvec) . qW2 + qb2  (one warp/edge)
// ---------------------------------------------------------------------------
__global__ void predict_kernel(const void* __restrict__ pidx,
                               const float* __restrict__ qW2,
                               const float* __restrict__ qb2,
                               float* __restrict__ y, int EP) {
    int w = (blockIdx.x * blockDim.x + threadIdx.x) >> 5;
    int lane = threadIdx.x & 31;
    if (w >= EP) return;
    int is64 = g_pi64;
    int i = getidx(pidx, w, is64);
    int j = getidx(pidx, (long long)EP + w, is64);
    float4 u = ((const float4*)g_b0)[i * 32 + lane];
    float4 v = ((const float4*)g_b1)[j * 32 + lane];
    float4 b = ((const float4*)g_cvec)[lane];
    float4 q = ((const float4*)qW2)[lane];
    float h0 = fmaxf(u.x + v.x + b.x, 0.f);
    float h1 = fmaxf(u.y + v.y + b.y, 0.f);
    float h2 = fmaxf(u.z + v.z + b.z, 0.f);
    float h3 = fmaxf(u.w + v.w + b.w, 0.f);
    float p = h0 * q.x + h1 * q.y + h2 * q.z + h3 * q.w;
#pragma unroll
    for (int o = 16; o > 0; o >>= 1) p += __shfl_xor_sync(0xFFFFFFFFu, p, o);
    if (lane == 0) y[w] = p + qb2[0];
}

// ---------------------------------------------------------------------------
// Launch
// ---------------------------------------------------------------------------
extern "C" void kernel_launch(void* const* d_in, const int* in_sizes, int n_in,
                              void* d_out, int out_size) {
    const float* x   = (const float*)d_in[0];
    const void*  ei  = d_in[2];
    const void*  pi  = d_in[3];
    const float* Wl  = (const float*)d_in[4];
    const float* bl  = (const float*)d_in[5];
    const float* Wr  = (const float*)d_in[6];
    // d_in[7..10]: edge-update MLP params — dead code w.r.t. the output
    const float* pW1 = (const float*)d_in[11];
    const float* pb1 = (const float*)d_in[12];
    const float* pW2 = (const float*)d_in[13];
    const float* pb2 = (const float*)d_in[14];
    const float* qW1 = (const float*)d_in[15];
    const float* qb1 = (const float*)d_in[16];
    const float* qW2 = (const float*)d_in[17];
    const float* qb2 = (const float*)d_in[18];

    const int N  = in_sizes[0] / 128;
    const int E  = in_sizes[2] / 2;
    const int EP = in_sizes[3] / 2;
    const int L  = in_sizes[4] / (128 * 128);

    cudaFuncSetAttribute(gemm_mma, cudaFuncAttributeMaxDynamicSharedMemorySize,
                         GEMM_SMEM_BYTES);

    // Fused setup: convert_x | prep_w | composite | cvec | init (one launch)
    const int n32 = N * 32;
    const int B_CONV = (n32 + 255) / 256;
    const int B_INIT = (N + 255) / 256;
    const int B_TOT = B_CONV + 576 + 128 + 1 + B_INIT;
    setup_kernel<<<B_TOT, 256>>>(x, n32, Wl, Wr, pW1, pW2, qW1, pb2, qb1,
                                 (const unsigned int*)ei,
                                 (const unsigned int*)pi, N, B_CONV, B_INIT);

    // CSR build
    count_kernel<<<(E + 255) / 256, 256>>>(ei, E);
    segment_kernel<<<(N + 255) / 256, 256>>>(N);
    fill_kernel<<<(E + 255) / 256, 256>>>(ei, E);

    const int gb = (N + 127) / 128;   // 391
    const int aggr_blocks = (N * 32 + 255) / 256;

    // GNN layers: cur pair sel 0(x) -> 1 -> 2 -> 1
    int cur = 0;
    for (int l = 0; l < L; l++) {
        int nxt = (l == 0) ? 1 : (l == 1) ? 2 : 1;
        aggr_kernel<<<aggr_blocks, 256>>>(cur, N);
        gemm_mma<<<dim3(gb, 1), 256, GEMM_SMEM_BYTES>>>(
            3, cur, l * 8, 0, bl + l * 128, 1, 0, nxt, 0, N);
        cur = nxt;
    }
    // cur = 1. Post MLP first half: z = relu(p0@pW1 + pb1) -> sel 2
    gemm_mma<<<dim3(gb, 1), 256, GEMM_SMEM_BYTES>>>(
        1, -1, 24, 0, pb1, 1, 0, 2, 0, N);
    // U/V from z with composite weights: y=0 -> W_U -> g_b0 ; y=1 -> W_V -> g_b1
    gemm_mma<<<dim3(gb, 2), 256, GEMM_SMEM_BYTES>>>(
        2, -1, 36, 40, nullptr, 0, 1, 0, 1, N);

    predict_kernel<<<(EP * 32 + 255) / 256, 256>>>(pi, qW2, qb2, (float*)d_out, EP);
}